// round 13
// baseline (speedup 1.0000x reference)
#include <cuda_runtime.h>

#define MAX_V 50000
#define MAX_E 200000
#define NB 148
#define TPB 1024

// Scratch (device globals — no allocation allowed in kernel_launch).
__device__ __align__(16) float g_vb[3][MAX_V * 8];
__device__ __align__(16) float g_msg[MAX_E * 16];
__device__ unsigned g_bar_count = 0;
__device__ volatile unsigned g_bar_gen = 0;

#define Q_SCALE 4096.0f
#define Q_INV   2.44140625e-4f

__device__ __forceinline__ float neg_inf() { return __int_as_float(0xff800000); }

__device__ __forceinline__ float2 dq16(unsigned w) {
    return make_float2((float)(short)(w & 0xFFFFu) * Q_INV,
                       (float)(short)(w >> 16) * Q_INV);
}
__device__ __forceinline__ void stg_cs4(float* p, float4 v) {
    asm volatile("st.global.cs.v4.f32 [%0], {%1,%2,%3,%4};"
                 :: "l"(p), "f"(v.x), "f"(v.y), "f"(v.z), "f"(v.w));
}
__device__ __forceinline__ void red_add_v2(float* p, float a, float b) {
    asm volatile("red.global.add.v2.f32 [%0], {%1, %2};"
                 :: "l"(p), "f"(a), "f"(b) : "memory");
}

// Sense-reversing device-wide barrier. Safe: grid=148 blocks, 1 block/SM
// (184KB smem) on a 152-SM chip -> all blocks co-resident.
__device__ __forceinline__ void grid_barrier() {
    __syncthreads();
    if (threadIdx.x == 0) {
        __threadfence();                      // release prior writes
        unsigned gen = g_bar_gen;
        if (atomicAdd(&g_bar_count, 1u) == (unsigned)(gridDim.x - 1)) {
            g_bar_count = 0;
            __threadfence();
            g_bar_gen = gen + 1;
        } else {
            while (g_bar_gen == gen) __nanosleep(64);
        }
        __threadfence();                      // acquire others' writes
    }
    __syncthreads();
}

// One edge update (R11-proven math). 4 lanes/edge, lane l owns states 2l,2l+1.
// Pairwise q16 comes from SMEM. Messages: im* on FIRST, g_msg otherwise.
template <bool FIRST, bool LAST>
__device__ __forceinline__ void edge_body(
    int il, int l, unsigned gm, int e0,
    const short* __restrict__ s_pw,
    const int* __restrict__ s_eu, const int* __restrict__ s_ev,
    const float* __restrict__ rd, float* __restrict__ wr,
    const float* __restrict__ im0, const float* __restrict__ im1,
    const unsigned char* __restrict__ fmask, float* __restrict__ out_fb) {
    int e = e0 + il;
    int u = s_eu[il], v = s_ev[il];

    float m00, m01, m10, m11;
    if (FIRST) {
        float2 aa = *reinterpret_cast<const float2*>(im0 + (size_t)e * 8 + 2 * l);
        float2 bb = *reinterpret_cast<const float2*>(im1 + (size_t)e * 8 + 2 * l);
        m00 = aa.x; m01 = aa.y; m10 = bb.x; m11 = bb.y;
    } else {
        float4 mm = *reinterpret_cast<const float4*>(g_msg + (size_t)e * 16 + l * 4);
        m00 = mm.x; m01 = mm.y; m10 = mm.z; m11 = mm.w;
    }
    float2 vbu = *reinterpret_cast<const float2*>(rd + (size_t)u * 8 + 2 * l);
    float2 vbv = *reinterpret_cast<const float2*>(rd + (size_t)v * 8 + 2 * l);
    float nu0 = vbu.x - m00, nu1 = vbu.y - m01;
    float nv0 = vbv.x - m10, nv1 = vbv.y - m11;

    // Rows 2l, 2l+1 as 8 packed q16 words from SMEM (two LDS.128).
    const uint4* qp = reinterpret_cast<const uint4*>(s_pw + (size_t)il * 64 + 16 * l);
    uint4 q0 = qp[0], q1 = qp[1];
    unsigned qw[8] = {q0.x, q0.y, q0.z, q0.w, q1.x, q1.y, q1.z, q1.w};

    float nm00, nm01, a[8];
    if (!LAST) {
        // Slim path: decode on the fly, stream the nv shuffles.
        nm00 = neg_inf(); nm01 = neg_inf();
#pragma unroll
        for (int p = 0; p < 4; p++) {
            float nva = __shfl_sync(gm, nv0, p, 4);
            float nvb = __shfl_sync(gm, nv1, p, 4);
            float2 r0 = dq16(qw[p]);
            float2 r1 = dq16(qw[p + 4]);
            nm00 = fmaxf(nm00, fmaxf(r0.x + nva, r0.y + nvb));
            nm01 = fmaxf(nm01, fmaxf(r1.x + nva, r1.y + nvb));
            a[2 * p]     = fmaxf(r0.x + nu0, r1.x + nu1);
            a[2 * p + 1] = fmaxf(r0.y + nu0, r1.y + nu1);
        }
    } else {
        // Full path (needs rows + nvv for the fb epilogue).
        float row0[8], row1[8], nvv[8];
#pragma unroll
        for (int j = 0; j < 4; j++) {
            float2 d0 = dq16(qw[j]);
            row0[2 * j] = d0.x; row0[2 * j + 1] = d0.y;
            float2 d1 = dq16(qw[j + 4]);
            row1[2 * j] = d1.x; row1[2 * j + 1] = d1.y;
            nvv[2 * j]     = __shfl_sync(gm, nv0, j, 4);
            nvv[2 * j + 1] = __shfl_sync(gm, nv1, j, 4);
        }
        nm00 = neg_inf(); nm01 = neg_inf();
#pragma unroll
        for (int j = 0; j < 8; j++) {
            nm00 = fmaxf(nm00, row0[j] + nvv[j]);
            nm01 = fmaxf(nm01, row1[j] + nvv[j]);
            a[j] = fmaxf(row0[j] + nu0, row1[j] + nu1);
        }
        // Factor beliefs; mask; softmax over all 64.
        const unsigned char* fm = fmask + (size_t)e * 64 + 16 * l;
        uint4 mq = *reinterpret_cast<const uint4*>(fm);
        unsigned mw[4] = {mq.x, mq.y, mq.z, mq.w};
        float fb0[8], fb1[8];
#pragma unroll
        for (int j = 0; j < 8; j++) {
            float x0 = row0[j] + nu0 + nvv[j];
            float x1 = row1[j] + nu1 + nvv[j];
            if ((mw[j >> 2] >> ((j & 3) * 8)) & 0xFFu) x0 = neg_inf();
            if ((mw[2 + (j >> 2)] >> ((j & 3) * 8)) & 0xFFu) x1 = neg_inf();
            fb0[j] = x0; fb1[j] = x1;
        }
        float gmax = neg_inf();
#pragma unroll
        for (int j = 0; j < 8; j++) gmax = fmaxf(gmax, fmaxf(fb0[j], fb1[j]));
        gmax = fmaxf(gmax, __shfl_xor_sync(gm, gmax, 1, 4));
        gmax = fmaxf(gmax, __shfl_xor_sync(gm, gmax, 2, 4));
        float s = 0.f;
#pragma unroll
        for (int j = 0; j < 8; j++) {
            fb0[j] = __expf(fb0[j] - gmax);
            fb1[j] = __expf(fb1[j] - gmax);
            s += fb0[j] + fb1[j];
        }
        s += __shfl_xor_sync(gm, s, 1, 4);
        s += __shfl_xor_sync(gm, s, 2, 4);
        float inv = 1.0f / s;
        float* op = out_fb + (size_t)e * 64 + 16 * l;
        stg_cs4(op,      make_float4(fb0[0] * inv, fb0[1] * inv, fb0[2] * inv, fb0[3] * inv));
        stg_cs4(op + 4,  make_float4(fb0[4] * inv, fb0[5] * inv, fb0[6] * inv, fb0[7] * inv));
        stg_cs4(op + 8,  make_float4(fb1[0] * inv, fb1[1] * inv, fb1[2] * inv, fb1[3] * inv));
        stg_cs4(op + 12, make_float4(fb1[4] * inv, fb1[5] * inv, fb1[6] * inv, fb1[7] * inv));
    }

    // Reduce-scatter column maxes over 4 lanes (6 shfls).
#pragma unroll
    for (int j = 0; j < 4; j++) {
        float send = (l & 2) ? a[j] : a[j + 4];
        float keep = (l & 2) ? a[j + 4] : a[j];
        float r = __shfl_xor_sync(gm, send, 2, 4);
        a[j] = fmaxf(keep, r);
    }
#pragma unroll
    for (int j = 0; j < 2; j++) {
        float send = (l & 1) ? a[j] : a[j + 2];
        float keep = (l & 1) ? a[j + 2] : a[j];
        float r = __shfl_xor_sync(gm, send, 1, 4);
        a[j] = fmaxf(keep, r);
    }
    float nm10 = a[0], nm11 = a[1];

    // Normalization maxes (2-stage butterflies, width 4).
    float mx0 = fmaxf(nm00, nm01);
    mx0 = fmaxf(mx0, __shfl_xor_sync(gm, mx0, 1, 4));
    mx0 = fmaxf(mx0, __shfl_xor_sync(gm, mx0, 2, 4));
    float mx1 = fmaxf(nm10, nm11);
    mx1 = fmaxf(mx1, __shfl_xor_sync(gm, mx1, 1, 4));
    mx1 = fmaxf(mx1, __shfl_xor_sync(gm, mx1, 2, 4));

    float o00 = 0.5f * m00 + 0.5f * (nm00 - mx0);
    float o01 = 0.5f * m01 + 0.5f * (nm01 - mx0);
    float o10 = 0.5f * m10 + 0.5f * (nm10 - mx1);
    float o11 = 0.5f * m11 + 0.5f * (nm11 - mx1);
    *reinterpret_cast<float4*>(g_msg + (size_t)e * 16 + l * 4) =
        make_float4(o00, o01, o10, o11);

    red_add_v2(wr + (size_t)u * 8 + 2 * l, o00, o01);
    red_add_v2(wr + (size_t)v * 8 + 2 * l, o10, o11);
}

__global__ void __launch_bounds__(TPB, 1) bp_persistent(
    const float* __restrict__ unary, const float* __restrict__ pairwise,
    const float* __restrict__ im0, const float* __restrict__ im1,
    const int* __restrict__ eu, const int* __restrict__ ev,
    const unsigned char* __restrict__ vmask,
    const unsigned char* __restrict__ fmask,
    float* __restrict__ out_vb, float* __restrict__ out_fb,
    int V, int E, int EB) {
    extern __shared__ __align__(16) char smem[];
    short* s_pw = (short*)smem;                         // EB*64 q16 values
    int* s_eu = (int*)(smem + (size_t)EB * 128);
    int* s_ev = s_eu + EB;

    int b = blockIdx.x;
    int e0 = b * EB;
    int ne = E - e0;
    if (ne < 0) ne = 0;
    if (ne > EB) ne = EB;

    float* b0 = g_vb[0];
    float* b1 = g_vb[1];
    float* b2 = g_vb[2];

    // Phase 0a: quantize this block's pairwise slice into SMEM (coalesced
    // float2 reads, linear u32 SMEM writes); load eu/ev; fill vb bufs 0,2.
    for (int i = threadIdx.x; i < ne * 32; i += TPB) {
        float2 p = *reinterpret_cast<const float2*>(
            pairwise + (size_t)e0 * 64 + (size_t)i * 2);
        int qa = __float2int_rn(fminf(fmaxf(p.x * Q_SCALE, -32767.f), 32767.f));
        int qb = __float2int_rn(fminf(fmaxf(p.y * Q_SCALE, -32767.f), 32767.f));
        ((unsigned*)s_pw)[i] = (unsigned)(qa & 0xFFFF) | ((unsigned)qb << 16);
    }
    for (int i = threadIdx.x; i < ne; i += TPB) {
        s_eu[i] = eu[e0 + i];
        s_ev[i] = ev[e0 + i];
    }
    int FCH = (V * 2 + NB - 1) / NB;       // float4 chunks per block
    int f0 = b * FCH;
    int f1 = f0 + FCH; if (f1 > V * 2) f1 = V * 2;
    for (int i = f0 + threadIdx.x; i < f1; i += TPB) {
        float4 uq = reinterpret_cast<const float4*>(unary)[i];
        reinterpret_cast<float4*>(b2)[i] = uq;
        reinterpret_cast<float4*>(b0)[i] = uq;
    }
    grid_barrier();

    // Phase 0b: scatter init messages into b2 (no-op adds for zero init msgs).
    for (int i = threadIdx.x; i < ne * 8; i += TPB) {
        int il = i >> 3, sl = i & 7;
        atomicAdd(b2 + (size_t)s_eu[il] * 8 + sl, im0[(size_t)(e0 + il) * 8 + sl]);
        atomicAdd(b2 + (size_t)s_ev[il] * 8 + sl, im1[(size_t)(e0 + il) * 8 + sl]);
    }
    grid_barrier();

    const unsigned gm = 0xFu << (threadIdx.x & 28);
    const int l = threadIdx.x & 3;
    const int ngs = ne * 4;   // lane-slots this block

    // Step 0 (FIRST): rd=b2, wr=b0, fill b1.
    for (int i = f0 + threadIdx.x; i < f1; i += TPB)
        reinterpret_cast<float4*>(b1)[i] = reinterpret_cast<const float4*>(unary)[i];
    for (int s = threadIdx.x; s < ngs; s += TPB)
        edge_body<true, false>(s >> 2, l, gm, e0, s_pw, s_eu, s_ev,
                               b2, b0, im0, im1, fmask, out_fb);
    grid_barrier();

    // Steps 1..5: rd=(k+2)%3, wr=k%3, fill (k+1)%3.
    float* bufs[3] = {b0, b1, b2};
    for (int k = 1; k < 6; k++) {
        const float* rd = bufs[(k + 2) % 3];
        float* wr = bufs[k % 3];
        float* fl = bufs[(k + 1) % 3];
        for (int i = f0 + threadIdx.x; i < f1; i += TPB)
            reinterpret_cast<float4*>(fl)[i] =
                reinterpret_cast<const float4*>(unary)[i];
        for (int s = threadIdx.x; s < ngs; s += TPB)
            edge_body<false, false>(s >> 2, l, gm, e0, s_pw, s_eu, s_ev,
                                    rd, wr, im0, im1, fmask, out_fb);
        grid_barrier();
    }

    // Step 6 (LAST): rd=b2, wr=b0, fb epilogue fused; no fill.
    for (int s = threadIdx.x; s < ngs; s += TPB)
        edge_body<false, true>(s >> 2, l, gm, e0, s_pw, s_eu, s_ev,
                               b2, b0, im0, im1, fmask, out_fb);
    grid_barrier();

    // Epilogue: calibrated var beliefs from b0 (masked softmax over S=8).
    int VCH = (V + NB - 1) / NB;
    int v0 = b * VCH;
    int v1 = v0 + VCH; if (v1 > V) v1 = V;
    for (int x = v0 + threadIdx.x; x < v1; x += TPB) {
        float4 aa = *reinterpret_cast<const float4*>(b0 + (size_t)x * 8);
        float4 bb = *reinterpret_cast<const float4*>(b0 + (size_t)x * 8 + 4);
        float r[8] = {aa.x, aa.y, aa.z, aa.w, bb.x, bb.y, bb.z, bb.w};
        uint2 mq = *reinterpret_cast<const uint2*>(vmask + (size_t)x * 8);
        unsigned mw[2] = {mq.x, mq.y};
#pragma unroll
        for (int q = 0; q < 2; q++)
#pragma unroll
            for (int bbt = 0; bbt < 4; bbt++)
                if ((mw[q] >> (8 * bbt)) & 0xFFu) r[q * 4 + bbt] = neg_inf();
        float m = neg_inf();
#pragma unroll
        for (int i = 0; i < 8; i++) m = fmaxf(m, r[i]);
        float s = 0.f;
#pragma unroll
        for (int i = 0; i < 8; i++) {
            r[i] = __expf(r[i] - m);
            s += r[i];
        }
        float inv = 1.0f / s;
        float* op = out_vb + (size_t)x * 8;
        stg_cs4(op,     make_float4(r[0] * inv, r[1] * inv, r[2] * inv, r[3] * inv));
        stg_cs4(op + 4, make_float4(r[4] * inv, r[5] * inv, r[6] * inv, r[7] * inv));
    }
}

extern "C" void kernel_launch(void* const* d_in, const int* in_sizes, int n_in,
                              void* d_out, int out_size) {
    const float* unary         = (const float*)d_in[0];
    const float* pairwise      = (const float*)d_in[1];
    const float* init_m        = (const float*)d_in[2];
    const int* eidx            = (const int*)d_in[3];
    const unsigned char* vmask = (const unsigned char*)d_in[4];
    const unsigned char* fmask = (const unsigned char*)d_in[5];

    int V = in_sizes[0] / 8;
    int E = in_sizes[1] / 64;
    const int* eu = eidx;
    const int* ev = eidx + E;
    const float* im0 = init_m;
    const float* im1 = init_m + (size_t)E * 8;

    float* out_vb = (float*)d_out;
    float* out_fb = out_vb + (size_t)V * 8;

    int EB = (E + NB - 1) / NB;                                // 1352
    size_t smem_bytes = (size_t)EB * 128 + (size_t)2 * EB * 4; // 183,872 B

    cudaFuncSetAttribute(bp_persistent,
                         cudaFuncAttributeMaxDynamicSharedMemorySize,
                         (int)smem_bytes);

    bp_persistent<<<NB, TPB, smem_bytes>>>(unary, pairwise, im0, im1, eu, ev,
                                           vmask, fmask, out_vb, out_fb,
                                           V, E, EB);
}

// round 14
// speedup vs baseline: 1.0757x; 1.0757x over previous
#include <cuda_runtime.h>

#define MAX_V 50000
#define MAX_E 200000

// Scratch (device globals — no allocation allowed in kernel_launch).
__device__ __align__(16) float g_vb[3][MAX_V * 8];
// Messages: edge e, lane l holds float4 {m0[2l],m0[2l+1],m1[2l],m1[2l+1]}.
__device__ __align__(16) float g_msg[MAX_E * 16];
// int16-quantized pairwise (scale 4096).
__device__ __align__(16) short g_pw16[MAX_E * 64];

#define Q_SCALE 4096.0f
#define Q_INV   2.44140625e-4f

__device__ __forceinline__ float neg_inf() { return __int_as_float(0xff800000); }

__device__ __forceinline__ float2 dq16(unsigned w) {
    return make_float2((float)(short)(w & 0xFFFFu) * Q_INV,
                       (float)(short)(w >> 16) * Q_INV);
}
__device__ __forceinline__ void stg_cs4(float* p, float4 v) {
    asm volatile("st.global.cs.v4.f32 [%0], {%1,%2,%3,%4};"
                 :: "l"(p), "f"(v.x), "f"(v.y), "f"(v.z), "f"(v.w));
}
__device__ __forceinline__ void red_add_v2(float* p, float a, float b) {
    asm volatile("red.global.add.v2.f32 [%0], {%1, %2};"
                 :: "l"(p), "f"(a), "f"(b) : "memory");
}

// Lane-per-state init scatter; also fills bufs[0] with unary.
__global__ void scatter_init_lane(const float* __restrict__ m0,
                                  const float* __restrict__ m1,
                                  const int* __restrict__ eu,
                                  const int* __restrict__ ev,
                                  float* __restrict__ vb,
                                  float* __restrict__ fill,
                                  const float* __restrict__ unary,
                                  int nfill4, int E) {
    int t = blockIdx.x * blockDim.x + threadIdx.x;
    if (t < nfill4)
        reinterpret_cast<float4*>(fill)[t] =
            reinterpret_cast<const float4*>(unary)[t];
    int e = t >> 3, l = t & 7;
    if (e >= E) return;
    atomicAdd(vb + (size_t)eu[e] * 8 + l, m0[(size_t)e * 8 + l]);
    atomicAdd(vb + (size_t)ev[e] * 8 + l, m1[(size_t)e * 8 + l]);
}

// ---------------- FIRST / LAST steps: proven 1-edge form (R11) -------------
template <bool FIRST, bool LAST>
__global__ void __launch_bounds__(128)
bp_lane4_kernel(const float* __restrict__ vb_cur,
                const float* __restrict__ pairwise,
                const int* __restrict__ eu,
                const int* __restrict__ ev,
                const float* __restrict__ im0,
                const float* __restrict__ im1,
                float* __restrict__ vb_next,
                float* __restrict__ fill,
                const float* __restrict__ unary,
                int nfill4,
                const unsigned char* __restrict__ fmask,
                float* __restrict__ out_fb, int E) {
    int t = blockIdx.x * blockDim.x + threadIdx.x;
    if (t < nfill4)
        reinterpret_cast<float4*>(fill)[t] =
            reinterpret_cast<const float4*>(unary)[t];

    int e = t >> 2, l = t & 3;
    if (e >= E) return;
    unsigned gm = 0xFu << (threadIdx.x & 28);

    int u = eu[e], v = ev[e];

    float m00, m01, m10, m11;
    if (FIRST) {
        float2 a = *reinterpret_cast<const float2*>(im0 + (size_t)e * 8 + 2 * l);
        float2 b = *reinterpret_cast<const float2*>(im1 + (size_t)e * 8 + 2 * l);
        m00 = a.x; m01 = a.y; m10 = b.x; m11 = b.y;
    } else {
        float4 mm = *reinterpret_cast<const float4*>(g_msg + (size_t)e * 16 + l * 4);
        m00 = mm.x; m01 = mm.y; m10 = mm.z; m11 = mm.w;
    }
    float2 vbu = *reinterpret_cast<const float2*>(vb_cur + (size_t)u * 8 + 2 * l);
    float2 vbv = *reinterpret_cast<const float2*>(vb_cur + (size_t)v * 8 + 2 * l);
    float nu0 = vbu.x - m00, nu1 = vbu.y - m01;
    float nv0 = vbv.x - m10, nv1 = vbv.y - m11;

    float row0[8], row1[8];
    if (FIRST) {
        const float* Pe = pairwise + (size_t)e * 64 + 2 * l * 8;
        float4 p0 = __ldg((const float4*)Pe);
        float4 p1 = __ldg((const float4*)(Pe + 4));
        float4 p2 = __ldg((const float4*)(Pe + 8));
        float4 p3 = __ldg((const float4*)(Pe + 12));
        float rf[16] = {p0.x, p0.y, p0.z, p0.w, p1.x, p1.y, p1.z, p1.w,
                        p2.x, p2.y, p2.z, p2.w, p3.x, p3.y, p3.z, p3.w};
        unsigned qw[8];
#pragma unroll
        for (int j = 0; j < 8; j++) {
            int qa = __float2int_rn(fminf(fmaxf(rf[2 * j]     * Q_SCALE, -32767.f), 32767.f));
            int qb = __float2int_rn(fminf(fmaxf(rf[2 * j + 1] * Q_SCALE, -32767.f), 32767.f));
            qw[j] = (unsigned)(qa & 0xFFFF) | ((unsigned)qb << 16);
        }
        short* qp = g_pw16 + (size_t)e * 64 + 16 * l;
        *reinterpret_cast<uint4*>(qp)     = make_uint4(qw[0], qw[1], qw[2], qw[3]);
        *reinterpret_cast<uint4*>(qp + 8) = make_uint4(qw[4], qw[5], qw[6], qw[7]);
#pragma unroll
        for (int j = 0; j < 8; j++) {
            float2 d = dq16(qw[j]);
            if (j < 4) { row0[2 * j] = d.x; row0[2 * j + 1] = d.y; }
            else       { row1[2 * (j - 4)] = d.x; row1[2 * (j - 4) + 1] = d.y; }
        }
    } else {
        const short* qp = g_pw16 + (size_t)e * 64 + 16 * l;
        uint4 q0 = *reinterpret_cast<const uint4*>(qp);
        uint4 q1 = *reinterpret_cast<const uint4*>(qp + 8);
        unsigned qw[8] = {q0.x, q0.y, q0.z, q0.w, q1.x, q1.y, q1.z, q1.w};
#pragma unroll
        for (int j = 0; j < 4; j++) {
            float2 d0 = dq16(qw[j]);
            row0[2 * j] = d0.x; row0[2 * j + 1] = d0.y;
            float2 d1 = dq16(qw[j + 4]);
            row1[2 * j] = d1.x; row1[2 * j + 1] = d1.y;
        }
    }

    float nvv[8];
#pragma unroll
    for (int j = 0; j < 4; j++) {
        nvv[2 * j]     = __shfl_sync(gm, nv0, j, 4);
        nvv[2 * j + 1] = __shfl_sync(gm, nv1, j, 4);
    }

    float nm00 = neg_inf(), nm01 = neg_inf();
    float a[8];
#pragma unroll
    for (int j = 0; j < 8; j++) {
        nm00 = fmaxf(nm00, row0[j] + nvv[j]);
        nm01 = fmaxf(nm01, row1[j] + nvv[j]);
        a[j] = fmaxf(row0[j] + nu0, row1[j] + nu1);
    }

    if (LAST) {
        const unsigned char* fm = fmask + (size_t)e * 64 + 16 * l;
        uint4 mq = *reinterpret_cast<const uint4*>(fm);
        unsigned mw[4] = {mq.x, mq.y, mq.z, mq.w};
        float fb0[8], fb1[8];
#pragma unroll
        for (int j = 0; j < 8; j++) {
            float x0 = row0[j] + nu0 + nvv[j];
            float x1 = row1[j] + nu1 + nvv[j];
            if ((mw[j >> 2] >> ((j & 3) * 8)) & 0xFFu) x0 = neg_inf();
            if ((mw[2 + (j >> 2)] >> ((j & 3) * 8)) & 0xFFu) x1 = neg_inf();
            fb0[j] = x0; fb1[j] = x1;
        }
        float gmax = neg_inf();
#pragma unroll
        for (int j = 0; j < 8; j++) gmax = fmaxf(gmax, fmaxf(fb0[j], fb1[j]));
        gmax = fmaxf(gmax, __shfl_xor_sync(gm, gmax, 1, 4));
        gmax = fmaxf(gmax, __shfl_xor_sync(gm, gmax, 2, 4));
        float s = 0.f;
#pragma unroll
        for (int j = 0; j < 8; j++) {
            fb0[j] = __expf(fb0[j] - gmax);
            fb1[j] = __expf(fb1[j] - gmax);
            s += fb0[j] + fb1[j];
        }
        s += __shfl_xor_sync(gm, s, 1, 4);
        s += __shfl_xor_sync(gm, s, 2, 4);
        float inv = 1.0f / s;
        float* op = out_fb + (size_t)e * 64 + 16 * l;
        stg_cs4(op,      make_float4(fb0[0] * inv, fb0[1] * inv, fb0[2] * inv, fb0[3] * inv));
        stg_cs4(op + 4,  make_float4(fb0[4] * inv, fb0[5] * inv, fb0[6] * inv, fb0[7] * inv));
        stg_cs4(op + 8,  make_float4(fb1[0] * inv, fb1[1] * inv, fb1[2] * inv, fb1[3] * inv));
        stg_cs4(op + 12, make_float4(fb1[4] * inv, fb1[5] * inv, fb1[6] * inv, fb1[7] * inv));
    }

#pragma unroll
    for (int j = 0; j < 4; j++) {
        float send = (l & 2) ? a[j] : a[j + 4];
        float keep = (l & 2) ? a[j + 4] : a[j];
        float r = __shfl_xor_sync(gm, send, 2, 4);
        a[j] = fmaxf(keep, r);
    }
#pragma unroll
    for (int j = 0; j < 2; j++) {
        float send = (l & 1) ? a[j] : a[j + 2];
        float keep = (l & 1) ? a[j + 2] : a[j];
        float r = __shfl_xor_sync(gm, send, 1, 4);
        a[j] = fmaxf(keep, r);
    }
    float nm10 = a[0], nm11 = a[1];

    float mx0 = fmaxf(nm00, nm01);
    mx0 = fmaxf(mx0, __shfl_xor_sync(gm, mx0, 1, 4));
    mx0 = fmaxf(mx0, __shfl_xor_sync(gm, mx0, 2, 4));
    float mx1 = fmaxf(nm10, nm11);
    mx1 = fmaxf(mx1, __shfl_xor_sync(gm, mx1, 1, 4));
    mx1 = fmaxf(mx1, __shfl_xor_sync(gm, mx1, 2, 4));

    float o00 = 0.5f * m00 + 0.5f * (nm00 - mx0);
    float o01 = 0.5f * m01 + 0.5f * (nm01 - mx0);
    float o10 = 0.5f * m10 + 0.5f * (nm10 - mx1);
    float o11 = 0.5f * m11 + 0.5f * (nm11 - mx1);
    *reinterpret_cast<float4*>(g_msg + (size_t)e * 16 + l * 4) =
        make_float4(o00, o01, o10, o11);

    red_add_v2(vb_next + (size_t)u * 8 + 2 * l, o00, o01);
    red_add_v2(vb_next + (size_t)v * 8 + 2 * l, o10, o11);
}

// ------------- Middle steps: ILP-2, 4 lanes process edges 2p, 2p+1 ---------
__global__ void __launch_bounds__(128)
bp_mid2_kernel(const float* __restrict__ vb_cur,
               const int* __restrict__ eu,
               const int* __restrict__ ev,
               float* __restrict__ vb_next,
               float* __restrict__ fill,
               const float* __restrict__ unary,
               int nfill4, int E) {
    int t = blockIdx.x * blockDim.x + threadIdx.x;
    if (t < nfill4)
        reinterpret_cast<float4*>(fill)[t] =
            reinterpret_cast<const float4*>(unary)[t];

    int p = t >> 2, l = t & 3;
    int eA = p * 2;
    if (eA >= E) return;
    bool hasB = (eA + 1) < E;
    int eB = hasB ? eA + 1 : eA;
    unsigned gm = 0xFu << (threadIdx.x & 28);

    // ---- All loads up front (2x MLP; pair lines adjacent) ----
    int uA, vA, uB, vB;
    if (hasB) {
        int2 uu = *reinterpret_cast<const int2*>(eu + eA);
        int2 vv = *reinterpret_cast<const int2*>(ev + eA);
        uA = uu.x; uB = uu.y; vA = vv.x; vB = vv.y;
    } else {
        uA = uB = eu[eA]; vA = vB = ev[eA];
    }
    float4 mA = *reinterpret_cast<const float4*>(g_msg + (size_t)eA * 16 + l * 4);
    float4 mB = *reinterpret_cast<const float4*>(g_msg + (size_t)eB * 16 + l * 4);
    const uint4* qpA = reinterpret_cast<const uint4*>(g_pw16 + (size_t)eA * 64 + 16 * l);
    const uint4* qpB = reinterpret_cast<const uint4*>(g_pw16 + (size_t)eB * 64 + 16 * l);
    uint4 qA0 = qpA[0], qA1 = qpA[1];
    uint4 qB0 = qpB[0], qB1 = qpB[1];
    float2 vbuA = *reinterpret_cast<const float2*>(vb_cur + (size_t)uA * 8 + 2 * l);
    float2 vbvA = *reinterpret_cast<const float2*>(vb_cur + (size_t)vA * 8 + 2 * l);
    float2 vbuB = *reinterpret_cast<const float2*>(vb_cur + (size_t)uB * 8 + 2 * l);
    float2 vbvB = *reinterpret_cast<const float2*>(vb_cur + (size_t)vB * 8 + 2 * l);

    float nuA0 = vbuA.x - mA.x, nuA1 = vbuA.y - mA.y;
    float nvA0 = vbvA.x - mA.z, nvA1 = vbvA.y - mA.w;
    float nuB0 = vbuB.x - mB.x, nuB1 = vbuB.y - mB.y;
    float nvB0 = vbvB.x - mB.z, nvB1 = vbvB.y - mB.w;

    unsigned qwA[8] = {qA0.x, qA0.y, qA0.z, qA0.w, qA1.x, qA1.y, qA1.z, qA1.w};
    unsigned qwB[8] = {qB0.x, qB0.y, qB0.z, qB0.w, qB1.x, qB1.y, qB1.z, qB1.w};

    // ---- Stage 1: row maxes + column partials, A/B interleaved ----
    float nmA0 = neg_inf(), nmA1 = neg_inf(), nmB0 = neg_inf(), nmB1 = neg_inf();
    float aA[8], aB[8];
#pragma unroll
    for (int pp = 0; pp < 4; pp++) {
        float nvaA = __shfl_sync(gm, nvA0, pp, 4);
        float nvbA = __shfl_sync(gm, nvA1, pp, 4);
        float nvaB = __shfl_sync(gm, nvB0, pp, 4);
        float nvbB = __shfl_sync(gm, nvB1, pp, 4);
        float2 rA0 = dq16(qwA[pp]);
        float2 rA1 = dq16(qwA[pp + 4]);
        float2 rB0 = dq16(qwB[pp]);
        float2 rB1 = dq16(qwB[pp + 4]);
        nmA0 = fmaxf(nmA0, fmaxf(rA0.x + nvaA, rA0.y + nvbA));
        nmA1 = fmaxf(nmA1, fmaxf(rA1.x + nvaA, rA1.y + nvbA));
        aA[2 * pp]     = fmaxf(rA0.x + nuA0, rA1.x + nuA1);
        aA[2 * pp + 1] = fmaxf(rA0.y + nuA0, rA1.y + nuA1);
        nmB0 = fmaxf(nmB0, fmaxf(rB0.x + nvaB, rB0.y + nvbB));
        nmB1 = fmaxf(nmB1, fmaxf(rB1.x + nvaB, rB1.y + nvbB));
        aB[2 * pp]     = fmaxf(rB0.x + nuB0, rB1.x + nuB1);
        aB[2 * pp + 1] = fmaxf(rB0.y + nuB0, rB1.y + nuB1);
    }

    // ---- Stage 2: reduce-scatter column maxes, A/B interleaved ----
#pragma unroll
    for (int j = 0; j < 4; j++) {
        float sA = (l & 2) ? aA[j] : aA[j + 4];
        float kA = (l & 2) ? aA[j + 4] : aA[j];
        float sB = (l & 2) ? aB[j] : aB[j + 4];
        float kB = (l & 2) ? aB[j + 4] : aB[j];
        float rA = __shfl_xor_sync(gm, sA, 2, 4);
        float rB = __shfl_xor_sync(gm, sB, 2, 4);
        aA[j] = fmaxf(kA, rA);
        aB[j] = fmaxf(kB, rB);
    }
#pragma unroll
    for (int j = 0; j < 2; j++) {
        float sA = (l & 1) ? aA[j] : aA[j + 2];
        float kA = (l & 1) ? aA[j + 2] : aA[j];
        float sB = (l & 1) ? aB[j] : aB[j + 2];
        float kB = (l & 1) ? aB[j + 2] : aB[j];
        float rA = __shfl_xor_sync(gm, sA, 1, 4);
        float rB = __shfl_xor_sync(gm, sB, 1, 4);
        aA[j] = fmaxf(kA, rA);
        aB[j] = fmaxf(kB, rB);
    }
    float nmA10 = aA[0], nmA11 = aA[1];
    float nmB10 = aB[0], nmB11 = aB[1];

    // ---- Stage 3: normalization maxes, A/B interleaved ----
    float mxA0 = fmaxf(nmA0, nmA1);
    float mxB0 = fmaxf(nmB0, nmB1);
    mxA0 = fmaxf(mxA0, __shfl_xor_sync(gm, mxA0, 1, 4));
    mxB0 = fmaxf(mxB0, __shfl_xor_sync(gm, mxB0, 1, 4));
    mxA0 = fmaxf(mxA0, __shfl_xor_sync(gm, mxA0, 2, 4));
    mxB0 = fmaxf(mxB0, __shfl_xor_sync(gm, mxB0, 2, 4));
    float mxA1 = fmaxf(nmA10, nmA11);
    float mxB1 = fmaxf(nmB10, nmB11);
    mxA1 = fmaxf(mxA1, __shfl_xor_sync(gm, mxA1, 1, 4));
    mxB1 = fmaxf(mxB1, __shfl_xor_sync(gm, mxB1, 1, 4));
    mxA1 = fmaxf(mxA1, __shfl_xor_sync(gm, mxA1, 2, 4));
    mxB1 = fmaxf(mxB1, __shfl_xor_sync(gm, mxB1, 2, 4));

    // ---- Damping, stores, scatter ----
    float oA00 = 0.5f * mA.x + 0.5f * (nmA0 - mxA0);
    float oA01 = 0.5f * mA.y + 0.5f * (nmA1 - mxA0);
    float oA10 = 0.5f * mA.z + 0.5f * (nmA10 - mxA1);
    float oA11 = 0.5f * mA.w + 0.5f * (nmA11 - mxA1);
    *reinterpret_cast<float4*>(g_msg + (size_t)eA * 16 + l * 4) =
        make_float4(oA00, oA01, oA10, oA11);
    red_add_v2(vb_next + (size_t)uA * 8 + 2 * l, oA00, oA01);
    red_add_v2(vb_next + (size_t)vA * 8 + 2 * l, oA10, oA11);

    if (hasB) {
        float oB00 = 0.5f * mB.x + 0.5f * (nmB0 - mxB0);
        float oB01 = 0.5f * mB.y + 0.5f * (nmB1 - mxB0);
        float oB10 = 0.5f * mB.z + 0.5f * (nmB10 - mxB1);
        float oB11 = 0.5f * mB.w + 0.5f * (nmB11 - mxB1);
        *reinterpret_cast<float4*>(g_msg + (size_t)eB * 16 + l * 4) =
            make_float4(oB00, oB01, oB10, oB11);
        red_add_v2(vb_next + (size_t)uB * 8 + 2 * l, oB00, oB01);
        red_add_v2(vb_next + (size_t)vB * 8 + 2 * l, oB10, oB11);
    }
}

// Calibrated var beliefs: masked softmax over S=8, one thread per variable.
__global__ void vb_out_kernel(const float* __restrict__ vb,
                              const unsigned char* __restrict__ vmask,
                              float* __restrict__ out, int V) {
    int x = blockIdx.x * blockDim.x + threadIdx.x;
    if (x >= V) return;
    float4 a = *reinterpret_cast<const float4*>(vb + (size_t)x * 8);
    float4 b = *reinterpret_cast<const float4*>(vb + (size_t)x * 8 + 4);
    float r[8] = {a.x, a.y, a.z, a.w, b.x, b.y, b.z, b.w};
    uint2 mq = *reinterpret_cast<const uint2*>(vmask + (size_t)x * 8);
    unsigned mw[2] = {mq.x, mq.y};
#pragma unroll
    for (int q = 0; q < 2; q++)
#pragma unroll
        for (int bb = 0; bb < 4; bb++)
            if ((mw[q] >> (8 * bb)) & 0xFFu) r[q * 4 + bb] = neg_inf();
    float m = neg_inf();
#pragma unroll
    for (int i = 0; i < 8; i++) m = fmaxf(m, r[i]);
    float s = 0.f;
#pragma unroll
    for (int i = 0; i < 8; i++) {
        r[i] = __expf(r[i] - m);
        s += r[i];
    }
    float inv = 1.0f / s;
    float* op = out + (size_t)x * 8;
    stg_cs4(op,     make_float4(r[0] * inv, r[1] * inv, r[2] * inv, r[3] * inv));
    stg_cs4(op + 4, make_float4(r[4] * inv, r[5] * inv, r[6] * inv, r[7] * inv));
}

extern "C" void kernel_launch(void* const* d_in, const int* in_sizes, int n_in,
                              void* d_out, int out_size) {
    const float* unary         = (const float*)d_in[0];
    const float* pairwise      = (const float*)d_in[1];
    const float* init_m        = (const float*)d_in[2];
    const int* eidx            = (const int*)d_in[3];
    const unsigned char* vmask = (const unsigned char*)d_in[4];
    const unsigned char* fmask = (const unsigned char*)d_in[5];

    int V = in_sizes[0] / 8;
    int E = in_sizes[1] / 64;
    const int* eu = eidx;
    const int* ev = eidx + E;
    const float* im0 = init_m;
    const float* im1 = init_m + (size_t)E * 8;

    float* out_vb = (float*)d_out;
    float* out_fb = out_vb + (size_t)V * 8;

    float* vbb_base;
    cudaGetSymbolAddress((void**)&vbb_base, g_vb);
    float* bufs[3] = {vbb_base,
                      vbb_base + (size_t)MAX_V * 8,
                      vbb_base + (size_t)2 * MAX_V * 8};

    size_t vbb = (size_t)V * 8 * sizeof(float);
    int nfill4 = V * 2;
    int blocks8 = (E * 8 + 255) / 256;
    int sthreads = 128;
    int sblocks  = (E * 4 + sthreads - 1) / sthreads;            // 1-edge kernels
    int nPairs   = (E + 1) / 2;
    int mblocks  = (nPairs * 4 + sthreads - 1) / sthreads;       // ILP-2 kernel

    // Step 0 reads bufs[2] = unary + segment_sum(init msgs);
    // scatters into bufs[0] (filled with unary inside scatter_init).
    cudaMemcpyAsync(bufs[2], unary, vbb, cudaMemcpyDeviceToDevice, 0);
    scatter_init_lane<<<blocks8, 256>>>(im0, im1, eu, ev, bufs[2],
                                        bufs[0], unary, nfill4, E);

    // 7 steps: step k reads bufs[(k+2)%3], writes bufs[k%3], refills (k+1)%3.
    bp_lane4_kernel<true, false><<<sblocks, sthreads>>>(
        bufs[2], pairwise, eu, ev, im0, im1, bufs[0],
        bufs[1], unary, nfill4, fmask, out_fb, E);
    for (int k = 1; k < 6; k++) {
        float* rd = bufs[(k + 2) % 3];
        float* wr = bufs[k % 3];
        float* fl = bufs[(k + 1) % 3];
        bp_mid2_kernel<<<mblocks, sthreads>>>(rd, eu, ev, wr, fl, unary,
                                              nfill4, E);
    }
    bp_lane4_kernel<false, true><<<sblocks, sthreads>>>(
        bufs[2], pairwise, eu, ev, nullptr, nullptr, bufs[0],
        bufs[1], unary, 0, fmask, out_fb, E);

    // Final var beliefs live in bufs[6%3] = bufs[0].
    vb_out_kernel<<<(V + 127) / 128, 128>>>(bufs[0], vmask, out_vb, V);
}